// round 15
// baseline (speedup 1.0000x reference)
#include <cuda_runtime.h>
#include <cstdint>

#define NUM_LABELS 64
#define MAXN (2 * 192 * 256 * 256)   // 25,165,824 — reference shape
#define RED_CTAS 444                 // 3 CTAs per SM * 148 SMs
#define RED_THREADS 256

// Scratch (allocation-free rule: __device__ globals)
__device__ float  g_sums[NUM_LABELS];     // fallback path only
__device__ float  g_cnts[NUM_LABELS];     // fallback path only
__device__ float  g_delta[NUM_LABELS];
__device__ float2 g_part[RED_CTAS][NUM_LABELS];   // per-CTA partials (fast path)
__device__ unsigned char g_lab8[MAXN];    // compressed labels for the apply pass

// ---------------------------------------------------------------------------
// Kernel 1 (fast): per-label sum+count, no atomics, 4-byte bias-packed slots:
//   slot += fmaf(v, 2^-12, 1.0f)  -> integer part = count, frac*4096 = sum.
// Table acc[label*256 + tid]: 64KB smem, 3 CTAs/SM, conflict-free.
// Grid-stride (round 12: chunking is worse), software-pipelined UNROLL 3,
// parallel 4x epilogue (round 13 win).
// Cache plan (round-8 proven): tex/lab __ldcs; lab8 __stcg (25MB stays in L2
// for apply). PDL: trigger downstream launch after the streaming loop so
// delta's blocks ramp while our epilogues drain.
// ---------------------------------------------------------------------------
#define BIAS_SCALE (1.0f / 4096.0f)
#define UNROLL 3

__global__ void __launch_bounds__(RED_THREADS, 3)
reduce_k(const float4* __restrict__ tex4, const int4* __restrict__ lab4, int n4) {
    extern __shared__ float acc[];   // [64][256]
    const int tid = threadIdx.x;

    #pragma unroll
    for (int i = tid; i < NUM_LABELS * RED_THREADS; i += RED_THREADS)
        acc[i] = 0.0f;
    __syncthreads();

    unsigned int* lab8w = (unsigned int*)g_lab8;

    const int stride = gridDim.x * RED_THREADS;
    int i = blockIdx.x * RED_THREADS + tid;

    float4 t[UNROLL];
    int4   l[UNROLL];
    bool have = (i + (UNROLL - 1) * stride < n4);
    if (have) {
        #pragma unroll
        for (int u = 0; u < UNROLL; u++) t[u] = __ldcs(&tex4[i + u * stride]);
        #pragma unroll
        for (int u = 0; u < UNROLL; u++) l[u] = __ldcs(&lab4[i + u * stride]);
    }

    while (have) {
        const int icur = i;
        int inext = i + UNROLL * stride;
        bool have_next = (inext + (UNROLL - 1) * stride < n4);

        float4 t2[UNROLL];
        int4   l2[UNROLL];
        if (have_next) {   // issue next loads BEFORE the RMW chain
            #pragma unroll
            for (int u = 0; u < UNROLL; u++) t2[u] = __ldcs(&tex4[inext + u * stride]);
            #pragma unroll
            for (int u = 0; u < UNROLL; u++) l2[u] = __ldcs(&lab4[inext + u * stride]);
        }

        #pragma unroll
        for (int u = 0; u < UNROLL; u++) {
            __stcg(&lab8w[icur + u * stride],
                   (unsigned)l[u].x | ((unsigned)l[u].y << 8) |
                   ((unsigned)l[u].z << 16) | ((unsigned)l[u].w << 24));
            acc[l[u].x * RED_THREADS + tid] += fmaf(t[u].x, BIAS_SCALE, 1.0f);
            acc[l[u].y * RED_THREADS + tid] += fmaf(t[u].y, BIAS_SCALE, 1.0f);
            acc[l[u].z * RED_THREADS + tid] += fmaf(t[u].z, BIAS_SCALE, 1.0f);
            acc[l[u].w * RED_THREADS + tid] += fmaf(t[u].w, BIAS_SCALE, 1.0f);
        }

        #pragma unroll
        for (int u = 0; u < UNROLL; u++) { t[u] = t2[u]; l[u] = l2[u]; }
        i = inext;
        have = have_next;
    }

    // residue (fewer than UNROLL strides left)
    for (; i < n4; i += stride) {
        const float4 tt = __ldcs(&tex4[i]);
        const int4   ll = __ldcs(&lab4[i]);
        __stcg(&lab8w[i], (unsigned)ll.x | ((unsigned)ll.y << 8) |
                          ((unsigned)ll.z << 16) | ((unsigned)ll.w << 24));
        acc[ll.x * RED_THREADS + tid] += fmaf(tt.x, BIAS_SCALE, 1.0f);
        acc[ll.y * RED_THREADS + tid] += fmaf(tt.y, BIAS_SCALE, 1.0f);
        acc[ll.z * RED_THREADS + tid] += fmaf(tt.z, BIAS_SCALE, 1.0f);
        acc[ll.w * RED_THREADS + tid] += fmaf(tt.w, BIAS_SCALE, 1.0f);
    }

#if __CUDA_ARCH__ >= 900
    // Let the dependent delta kernel's blocks launch while epilogues drain.
    cudaTriggerProgrammaticLaunchCompletion();
#endif
    __syncthreads();

    // Parallel epilogue: thread t decodes quarter (t>>6) of label (t&63).
    {
        const int lbl = tid & 63;
        const int quarter = tid >> 6;            // 0..3
        const int base = lbl * RED_THREADS + quarter * 64;
        float s = 0.0f, c = 0.0f;
        #pragma unroll 8
        for (int k = 0; k < 64; k++) {
            int sp = (k + tid) & 63;             // staggered, conflict-free
            float a = acc[base + sp];
            float cnt = rintf(a);                // exact count (|frac| < 0.5)
            s += (a - cnt) * 4096.0f;
            c += cnt;
        }
        __syncthreads();                          // all reads done before overwrite
        acc[quarter * 64 + lbl] = s;              // reuse table as scratch
        acc[256 + quarter * 64 + lbl] = c;
        __syncthreads();
        if (tid < NUM_LABELS) {
            float S = acc[tid] + acc[64 + tid] + acc[128 + tid] + acc[192 + tid];
            float C = acc[256 + tid] + acc[320 + tid] + acc[384 + tid] + acc[448 + tid];
            g_part[blockIdx.x][tid] = make_float2(S, C);   // plain store, no atomics
        }
    }
}

// ---------------------------------------------------------------------------
// Kernel 2 (fast): block per label reduces 444 partials -> delta.
// PDL consumer: blocks may launch before reduce_k finishes; the grid-dep
// sync provides full ordering + memory visibility for g_part.
// ---------------------------------------------------------------------------
__global__ void __launch_bounds__(128) delta_fast_k(const float* __restrict__ inten) {
#if __CUDA_ARCH__ >= 900
    cudaTriggerProgrammaticLaunchCompletion();   // let apply's blocks ramp now
    cudaGridDependencySynchronize();             // wait for reduce_k + visibility
#endif
    __shared__ float sh_s[4], sh_c[4];
    const int l = blockIdx.x;
    const int tid = threadIdx.x;

    float s = 0.0f, c = 0.0f;
    for (int p = tid; p < RED_CTAS; p += 128) {
        float2 v = g_part[p][l];
        s += v.x; c += v.y;
    }
    #pragma unroll
    for (int o = 16; o > 0; o >>= 1) {
        s += __shfl_down_sync(0xFFFFFFFF, s, o);
        c += __shfl_down_sync(0xFFFFFFFF, c, o);
    }
    if ((tid & 31) == 0) { sh_s[tid >> 5] = s; sh_c[tid >> 5] = c; }
    __syncthreads();
    if (tid == 0) {
        s = sh_s[0] + sh_s[1] + sh_s[2] + sh_s[3];
        c = sh_c[0] + sh_c[1] + sh_c[2] + sh_c[3];
        float m = s / fmaxf(c, 1.0f);
        g_delta[l] = (l > 0) ? (m - inten[l]) : 0.0f;
    }
}

// ---------------------------------------------------------------------------
// Kernel 3 (fast): out = tex - delta[lab8], 2 float4 tiles per thread.
// PDL consumer: ramps concurrently with delta_fast_k, syncs before reading
// g_delta. tex/out evict-first; lab8 __ldcg (L2-resident).
// ---------------------------------------------------------------------------
__global__ void __launch_bounds__(256) apply_packed_k(const float4* __restrict__ tex4,
                                                      float4* __restrict__ out4,
                                                      int n4) {
#if __CUDA_ARCH__ >= 900
    cudaGridDependencySynchronize();             // wait for delta_fast_k
#endif
    __shared__ float sd[NUM_LABELS];
    if (threadIdx.x < NUM_LABELS) sd[threadIdx.x] = g_delta[threadIdx.x];
    __syncthreads();

    const unsigned int* lab8w = (const unsigned int*)g_lab8;
    int i0 = blockIdx.x * 512 + threadIdx.x;
    int i1 = i0 + 256;

    if (i1 < n4) {
        const float4 ta = __ldcs(&tex4[i0]);
        const float4 tb = __ldcs(&tex4[i1]);
        const unsigned int la = __ldcg(&lab8w[i0]);
        const unsigned int lb = __ldcg(&lab8w[i1]);
        float4 oa, ob;
        oa.x = ta.x - sd[la & 0xFF];
        oa.y = ta.y - sd[(la >> 8) & 0xFF];
        oa.z = ta.z - sd[(la >> 16) & 0xFF];
        oa.w = ta.w - sd[la >> 24];
        ob.x = tb.x - sd[lb & 0xFF];
        ob.y = tb.y - sd[(lb >> 8) & 0xFF];
        ob.z = tb.z - sd[(lb >> 16) & 0xFF];
        ob.w = tb.w - sd[lb >> 24];
        __stcs(&out4[i0], oa);
        __stcs(&out4[i1], ob);
    } else if (i0 < n4) {
        const float4 t = __ldcs(&tex4[i0]);
        const unsigned int l = __ldcg(&lab8w[i0]);
        float4 o;
        o.x = t.x - sd[l & 0xFF];
        o.y = t.y - sd[(l >> 8) & 0xFF];
        o.z = t.z - sd[(l >> 16) & 0xFF];
        o.w = t.w - sd[l >> 24];
        __stcs(&out4[i0], o);
    }
}

// ---------------------------------------------------------------------------
// Fallback path (n not 4-divisible or > MAXN): scalar, shared-atomic
// ---------------------------------------------------------------------------
__global__ void zero_k() {
    int i = threadIdx.x;
    if (i < NUM_LABELS) { g_sums[i] = 0.0f; g_cnts[i] = 0.0f; }
}

__global__ void __launch_bounds__(256) reduce_scalar_k(const float* __restrict__ tex,
                                                       const int*  __restrict__ lab,
                                                       int n) {
    __shared__ float2 accw[8][NUM_LABELS];
    const int w = threadIdx.x >> 5;
    for (int i = threadIdx.x; i < 8 * NUM_LABELS; i += 256)
        (&accw[0][0])[i] = make_float2(0.0f, 0.0f);
    __syncthreads();
    int i = blockIdx.x * 256 + threadIdx.x;
    const int stride = gridDim.x * 256;
    for (; i < n; i += stride) {
        atomicAdd(&accw[w][lab[i]].x, tex[i]);
        atomicAdd(&accw[w][lab[i]].y, 1.0f);
    }
    __syncthreads();
    for (int l = threadIdx.x; l < NUM_LABELS; l += 256) {
        float s = 0.0f, c = 0.0f;
        #pragma unroll
        for (int ww = 0; ww < 8; ww++) { s += accw[ww][l].x; c += accw[ww][l].y; }
        atomicAdd(&g_sums[l], s);
        atomicAdd(&g_cnts[l], c);
    }
}

__global__ void delta_k(const float* __restrict__ inten) {
    int l = threadIdx.x;
    if (l < NUM_LABELS) {
        float m = g_sums[l] / fmaxf(g_cnts[l], 1.0f);
        g_delta[l] = (l > 0) ? (m - inten[l]) : 0.0f;
    }
}

__global__ void __launch_bounds__(256) apply_scalar_k(const float* __restrict__ tex,
                                                      const int*  __restrict__ lab,
                                                      float* __restrict__ out,
                                                      int n) {
    __shared__ float sd[NUM_LABELS];
    if (threadIdx.x < NUM_LABELS) sd[threadIdx.x] = g_delta[threadIdx.x];
    __syncthreads();
    int i = blockIdx.x * 256 + threadIdx.x;
    if (i < n) out[i] = tex[i] - sd[lab[i]];
}

// ---------------------------------------------------------------------------
extern "C" void kernel_launch(void* const* d_in, const int* in_sizes, int n_in,
                              void* d_out, int out_size) {
    const float* tex   = (const float*)d_in[0];
    const int*   lab   = (const int*)  d_in[1];
    const float* inten = (const float*)d_in[2];
    float* out = (float*)d_out;

    const int n  = in_sizes[0];
    const int n4 = n >> 2;
    const bool fast = ((n & 3) == 0) && (n <= MAXN) && (n4 >= RED_CTAS * RED_THREADS);

    if (fast) {
        static int smem_set = 0;   // host-side one-time config
        const int smem_bytes = NUM_LABELS * RED_THREADS * (int)sizeof(float); // 64KB
        if (!smem_set) {
            cudaFuncSetAttribute(reduce_k, cudaFuncAttributeMaxDynamicSharedMemorySize,
                                 smem_bytes);
            smem_set = 1;
        }
        reduce_k<<<RED_CTAS, RED_THREADS, smem_bytes>>>((const float4*)tex,
                                                        (const int4*)lab, n4);

        // delta: PDL — overlap with reduce's epilogue drain
        {
            cudaLaunchConfig_t cfg = {};
            cfg.gridDim  = dim3(NUM_LABELS, 1, 1);
            cfg.blockDim = dim3(128, 1, 1);
            cudaLaunchAttribute attr[1];
            attr[0].id = cudaLaunchAttributeProgrammaticStreamSerialization;
            attr[0].val.programmaticStreamSerializationAllowed = 1;
            cfg.attrs = attr;
            cfg.numAttrs = 1;
            cudaLaunchKernelEx(&cfg, delta_fast_k, inten);
        }

        // apply: PDL — ramp its 12k blocks while delta runs
        {
            int app_blocks = (n4 + 511) / 512;
            cudaLaunchConfig_t cfg = {};
            cfg.gridDim  = dim3(app_blocks, 1, 1);
            cfg.blockDim = dim3(256, 1, 1);
            cudaLaunchAttribute attr[1];
            attr[0].id = cudaLaunchAttributeProgrammaticStreamSerialization;
            attr[0].val.programmaticStreamSerializationAllowed = 1;
            cfg.attrs = attr;
            cfg.numAttrs = 1;
            cudaLaunchKernelEx(&cfg, apply_packed_k,
                               (const float4*)tex, (float4*)out, n4);
        }
    } else {
        zero_k<<<1, 64>>>();
        reduce_scalar_k<<<1184, 256>>>(tex, lab, n);
        delta_k<<<1, 64>>>(inten);
        int app_blocks = (n + 255) / 256;
        apply_scalar_k<<<app_blocks, 256>>>(tex, lab, out, n);
    }
}

// round 16
// speedup vs baseline: 1.0043x; 1.0043x over previous
#include <cuda_runtime.h>
#include <cstdint>

#define NUM_LABELS 64
#define MAXN (2 * 192 * 256 * 256)   // 25,165,824 — reference shape
#define RED_CTAS 444                 // 3 CTAs per SM * 148 SMs
#define RED_THREADS 256

// Scratch (allocation-free rule: __device__ globals)
__device__ float  g_sums[NUM_LABELS];     // fallback path only
__device__ float  g_cnts[NUM_LABELS];     // fallback path only
__device__ float  g_delta[NUM_LABELS];
__device__ float2 g_part[RED_CTAS][NUM_LABELS];   // per-CTA partials (fast path)
__device__ unsigned char g_lab8[MAXN];    // compressed labels for the apply pass

// ---------------------------------------------------------------------------
// Kernel 1 (fast): per-label sum+count, no atomics, 4-byte bias-packed slots:
//   slot += fmaf(v, 2^-12, 1.0f)  -> integer part = count, frac*4096 = sum.
// Table acc[label*256 + tid]: 64KB smem, 3 CTAs/SM, conflict-free.
// Grid-stride (round 12: chunking worse), software-pipelined UNROLL 3,
// parallel 4x epilogue (round 13 win).
// Cache plan (round-8 proven): tex/lab __ldcs; lab8 __stcg (25MB stays in L2
// for apply; protected because all other streams are evict-first).
// PDL trigger after the streaming loop: ONLY the 64-block delta kernel is a
// PDL consumer (round 15: PDL on apply's 12k blocks made them spin-resident
// during reduce and cost ~2us).
// ---------------------------------------------------------------------------
#define BIAS_SCALE (1.0f / 4096.0f)
#define UNROLL 3

__global__ void __launch_bounds__(RED_THREADS, 3)
reduce_k(const float4* __restrict__ tex4, const int4* __restrict__ lab4, int n4) {
    extern __shared__ float acc[];   // [64][256]
    const int tid = threadIdx.x;

    #pragma unroll
    for (int i = tid; i < NUM_LABELS * RED_THREADS; i += RED_THREADS)
        acc[i] = 0.0f;
    __syncthreads();

    unsigned int* lab8w = (unsigned int*)g_lab8;

    const int stride = gridDim.x * RED_THREADS;
    int i = blockIdx.x * RED_THREADS + tid;

    float4 t[UNROLL];
    int4   l[UNROLL];
    bool have = (i + (UNROLL - 1) * stride < n4);
    if (have) {
        #pragma unroll
        for (int u = 0; u < UNROLL; u++) t[u] = __ldcs(&tex4[i + u * stride]);
        #pragma unroll
        for (int u = 0; u < UNROLL; u++) l[u] = __ldcs(&lab4[i + u * stride]);
    }

    while (have) {
        const int icur = i;
        int inext = i + UNROLL * stride;
        bool have_next = (inext + (UNROLL - 1) * stride < n4);

        float4 t2[UNROLL];
        int4   l2[UNROLL];
        if (have_next) {   // issue next loads BEFORE the RMW chain
            #pragma unroll
            for (int u = 0; u < UNROLL; u++) t2[u] = __ldcs(&tex4[inext + u * stride]);
            #pragma unroll
            for (int u = 0; u < UNROLL; u++) l2[u] = __ldcs(&lab4[inext + u * stride]);
        }

        #pragma unroll
        for (int u = 0; u < UNROLL; u++) {
            __stcg(&lab8w[icur + u * stride],
                   (unsigned)l[u].x | ((unsigned)l[u].y << 8) |
                   ((unsigned)l[u].z << 16) | ((unsigned)l[u].w << 24));
            acc[l[u].x * RED_THREADS + tid] += fmaf(t[u].x, BIAS_SCALE, 1.0f);
            acc[l[u].y * RED_THREADS + tid] += fmaf(t[u].y, BIAS_SCALE, 1.0f);
            acc[l[u].z * RED_THREADS + tid] += fmaf(t[u].z, BIAS_SCALE, 1.0f);
            acc[l[u].w * RED_THREADS + tid] += fmaf(t[u].w, BIAS_SCALE, 1.0f);
        }

        #pragma unroll
        for (int u = 0; u < UNROLL; u++) { t[u] = t2[u]; l[u] = l2[u]; }
        i = inext;
        have = have_next;
    }

    // residue (fewer than UNROLL strides left)
    for (; i < n4; i += stride) {
        const float4 tt = __ldcs(&tex4[i]);
        const int4   ll = __ldcs(&lab4[i]);
        __stcg(&lab8w[i], (unsigned)ll.x | ((unsigned)ll.y << 8) |
                          ((unsigned)ll.z << 16) | ((unsigned)ll.w << 24));
        acc[ll.x * RED_THREADS + tid] += fmaf(tt.x, BIAS_SCALE, 1.0f);
        acc[ll.y * RED_THREADS + tid] += fmaf(tt.y, BIAS_SCALE, 1.0f);
        acc[ll.z * RED_THREADS + tid] += fmaf(tt.z, BIAS_SCALE, 1.0f);
        acc[ll.w * RED_THREADS + tid] += fmaf(tt.w, BIAS_SCALE, 1.0f);
    }

#if __CUDA_ARCH__ >= 900
    // Allow the 64-block delta kernel to launch while epilogues drain.
    cudaTriggerProgrammaticLaunchCompletion();
#endif
    __syncthreads();

    // Parallel epilogue: thread t decodes quarter (t>>6) of label (t&63).
    {
        const int lbl = tid & 63;
        const int quarter = tid >> 6;            // 0..3
        const int base = lbl * RED_THREADS + quarter * 64;
        float s = 0.0f, c = 0.0f;
        #pragma unroll 8
        for (int k = 0; k < 64; k++) {
            int sp = (k + tid) & 63;             // staggered, conflict-free
            float a = acc[base + sp];
            float cnt = rintf(a);                // exact count (|frac| < 0.5)
            s += (a - cnt) * 4096.0f;
            c += cnt;
        }
        __syncthreads();                          // all reads done before overwrite
        acc[quarter * 64 + lbl] = s;              // reuse table as scratch
        acc[256 + quarter * 64 + lbl] = c;
        __syncthreads();
        if (tid < NUM_LABELS) {
            float S = acc[tid] + acc[64 + tid] + acc[128 + tid] + acc[192 + tid];
            float C = acc[256 + tid] + acc[320 + tid] + acc[384 + tid] + acc[448 + tid];
            g_part[blockIdx.x][tid] = make_float2(S, C);   // plain store, no atomics
        }
    }
}

// ---------------------------------------------------------------------------
// Kernel 2 (fast): block per label reduces 444 partials -> delta.
// PDL consumer (64 blocks only — negligible spin footprint): grid-dep sync
// provides full ordering + memory visibility for g_part.
// ---------------------------------------------------------------------------
__global__ void __launch_bounds__(128) delta_fast_k(const float* __restrict__ inten) {
#if __CUDA_ARCH__ >= 900
    cudaGridDependencySynchronize();             // wait for reduce_k + visibility
#endif
    __shared__ float sh_s[4], sh_c[4];
    const int l = blockIdx.x;
    const int tid = threadIdx.x;

    float s = 0.0f, c = 0.0f;
    for (int p = tid; p < RED_CTAS; p += 128) {
        float2 v = g_part[p][l];
        s += v.x; c += v.y;
    }
    #pragma unroll
    for (int o = 16; o > 0; o >>= 1) {
        s += __shfl_down_sync(0xFFFFFFFF, s, o);
        c += __shfl_down_sync(0xFFFFFFFF, c, o);
    }
    if ((tid & 31) == 0) { sh_s[tid >> 5] = s; sh_c[tid >> 5] = c; }
    __syncthreads();
    if (tid == 0) {
        s = sh_s[0] + sh_s[1] + sh_s[2] + sh_s[3];
        c = sh_c[0] + sh_c[1] + sh_c[2] + sh_c[3];
        float m = s / fmaxf(c, 1.0f);
        g_delta[l] = (l > 0) ? (m - inten[l]) : 0.0f;
    }
}

// ---------------------------------------------------------------------------
// Kernel 3 (fast): out = tex - delta[lab8], 2 float4 tiles per thread.
// NORMAL launch (round 15: PDL here regressed reduce). tex/out evict-first;
// lab8 __ldcg (L2-resident from reduce's __stcg).
// ---------------------------------------------------------------------------
__global__ void __launch_bounds__(256) apply_packed_k(const float4* __restrict__ tex4,
                                                      float4* __restrict__ out4,
                                                      int n4) {
    __shared__ float sd[NUM_LABELS];
    if (threadIdx.x < NUM_LABELS) sd[threadIdx.x] = g_delta[threadIdx.x];
    __syncthreads();

    const unsigned int* lab8w = (const unsigned int*)g_lab8;
    int i0 = blockIdx.x * 512 + threadIdx.x;
    int i1 = i0 + 256;

    if (i1 < n4) {
        const float4 ta = __ldcs(&tex4[i0]);
        const float4 tb = __ldcs(&tex4[i1]);
        const unsigned int la = __ldcg(&lab8w[i0]);
        const unsigned int lb = __ldcg(&lab8w[i1]);
        float4 oa, ob;
        oa.x = ta.x - sd[la & 0xFF];
        oa.y = ta.y - sd[(la >> 8) & 0xFF];
        oa.z = ta.z - sd[(la >> 16) & 0xFF];
        oa.w = ta.w - sd[la >> 24];
        ob.x = tb.x - sd[lb & 0xFF];
        ob.y = tb.y - sd[(lb >> 8) & 0xFF];
        ob.z = tb.z - sd[(lb >> 16) & 0xFF];
        ob.w = tb.w - sd[lb >> 24];
        __stcs(&out4[i0], oa);
        __stcs(&out4[i1], ob);
    } else if (i0 < n4) {
        const float4 t = __ldcs(&tex4[i0]);
        const unsigned int l = __ldcg(&lab8w[i0]);
        float4 o;
        o.x = t.x - sd[l & 0xFF];
        o.y = t.y - sd[(l >> 8) & 0xFF];
        o.z = t.z - sd[(l >> 16) & 0xFF];
        o.w = t.w - sd[l >> 24];
        __stcs(&out4[i0], o);
    }
}

// ---------------------------------------------------------------------------
// Fallback path (n not 4-divisible or > MAXN): scalar, shared-atomic
// ---------------------------------------------------------------------------
__global__ void zero_k() {
    int i = threadIdx.x;
    if (i < NUM_LABELS) { g_sums[i] = 0.0f; g_cnts[i] = 0.0f; }
}

__global__ void __launch_bounds__(256) reduce_scalar_k(const float* __restrict__ tex,
                                                       const int*  __restrict__ lab,
                                                       int n) {
    __shared__ float2 accw[8][NUM_LABELS];
    const int w = threadIdx.x >> 5;
    for (int i = threadIdx.x; i < 8 * NUM_LABELS; i += 256)
        (&accw[0][0])[i] = make_float2(0.0f, 0.0f);
    __syncthreads();
    int i = blockIdx.x * 256 + threadIdx.x;
    const int stride = gridDim.x * 256;
    for (; i < n; i += stride) {
        atomicAdd(&accw[w][lab[i]].x, tex[i]);
        atomicAdd(&accw[w][lab[i]].y, 1.0f);
    }
    __syncthreads();
    for (int l = threadIdx.x; l < NUM_LABELS; l += 256) {
        float s = 0.0f, c = 0.0f;
        #pragma unroll
        for (int ww = 0; ww < 8; ww++) { s += accw[ww][l].x; c += accw[ww][l].y; }
        atomicAdd(&g_sums[l], s);
        atomicAdd(&g_cnts[l], c);
    }
}

__global__ void delta_k(const float* __restrict__ inten) {
    int l = threadIdx.x;
    if (l < NUM_LABELS) {
        float m = g_sums[l] / fmaxf(g_cnts[l], 1.0f);
        g_delta[l] = (l > 0) ? (m - inten[l]) : 0.0f;
    }
}

__global__ void __launch_bounds__(256) apply_scalar_k(const float* __restrict__ tex,
                                                      const int*  __restrict__ lab,
                                                      float* __restrict__ out,
                                                      int n) {
    __shared__ float sd[NUM_LABELS];
    if (threadIdx.x < NUM_LABELS) sd[threadIdx.x] = g_delta[threadIdx.x];
    __syncthreads();
    int i = blockIdx.x * 256 + threadIdx.x;
    if (i < n) out[i] = tex[i] - sd[lab[i]];
}

// ---------------------------------------------------------------------------
extern "C" void kernel_launch(void* const* d_in, const int* in_sizes, int n_in,
                              void* d_out, int out_size) {
    const float* tex   = (const float*)d_in[0];
    const int*   lab   = (const int*)  d_in[1];
    const float* inten = (const float*)d_in[2];
    float* out = (float*)d_out;

    const int n  = in_sizes[0];
    const int n4 = n >> 2;
    const bool fast = ((n & 3) == 0) && (n <= MAXN) && (n4 >= RED_CTAS * RED_THREADS);

    if (fast) {
        static int smem_set = 0;   // host-side one-time config
        const int smem_bytes = NUM_LABELS * RED_THREADS * (int)sizeof(float); // 64KB
        if (!smem_set) {
            cudaFuncSetAttribute(reduce_k, cudaFuncAttributeMaxDynamicSharedMemorySize,
                                 smem_bytes);
            smem_set = 1;
        }
        reduce_k<<<RED_CTAS, RED_THREADS, smem_bytes>>>((const float4*)tex,
                                                        (const int4*)lab, n4);

        // delta: PDL consumer (64 blocks) — overlaps reduce's epilogue drain
        {
            cudaLaunchConfig_t cfg = {};
            cfg.gridDim  = dim3(NUM_LABELS, 1, 1);
            cfg.blockDim = dim3(128, 1, 1);
            cudaLaunchAttribute attr[1];
            attr[0].id = cudaLaunchAttributeProgrammaticStreamSerialization;
            attr[0].val.programmaticStreamSerializationAllowed = 1;
            cfg.attrs = attr;
            cfg.numAttrs = 1;
            cudaLaunchKernelEx(&cfg, delta_fast_k, inten);
        }

        // apply: NORMAL launch (PDL here regressed reduce in round 15)
        int app_blocks = (n4 + 511) / 512;
        apply_packed_k<<<app_blocks, 256>>>((const float4*)tex, (float4*)out, n4);
    } else {
        zero_k<<<1, 64>>>();
        reduce_scalar_k<<<1184, 256>>>(tex, lab, n);
        delta_k<<<1, 64>>>(inten);
        int app_blocks = (n + 255) / 256;
        apply_scalar_k<<<app_blocks, 256>>>(tex, lab, out, n);
    }
}